// round 13
// baseline (speedup 1.0000x reference)
#include <cuda_runtime.h>
#include <cuda_bf16.h>
#include <mma.h>
#include <cstdint>

using namespace nvcuda;

#define NN   50000
#define NE   640000
#define HID  256
#define LD   72     // bf16 leading dim (144B stride -> conflict-free LDSM)

#define WOF_W1A 0
#define WOF_W1B 32768
#define WOF_W2  65536
#define WOF_W3  131072
#define WOF_W4  245760
#define WB_HALF 278528

__device__ __align__(16) __nv_bfloat16 g_wb[2 * WB_HALF];
__device__ float g_P[NN * HID];
__device__ float g_agg[NN * HID];
__device__ float g_hagg[NN * HID];
__device__ float g_cnt[NN];
__device__ int   g_is64;

// per-stage smem layout (bytes, relative to stage base):
//   Ah 0 | Al 18432 | Bh 36864 | Bl 55296 ; stage stride 73728; 2 stages
#define OFF_AL  18432
#define OFF_BH  36864
#define OFF_BL  55296
#define STG     73728
#define SMEM_TOTAL (2 * STG)   // 147456

// named barriers: 1,2 = stage full; 3,4 = stage empty (256 participants)
#define BAR_SYNC(id)   asm volatile("bar.sync %0, 256;"   :: "r"(id) : "memory")
#define BAR_ARRIVE(id) asm volatile("bar.arrive %0, 256;" :: "r"(id) : "memory")

// ---------------------------------------------------------------------------
__global__ void zero_kernel(const void* ei_raw) {
    int idx = blockIdx.x * blockDim.x + threadIdx.x;
    int stride = gridDim.x * blockDim.x;
    for (int i = idx; i < NN * HID; i += stride) g_agg[i] = 0.f;
    for (int i = idx; i < NN; i += stride) g_cnt[i] = 0.f;
    if (idx == 0) {
        const long long* p = (const long long*)ei_raw;
        int ok = 1;
        for (int i = 0; i < 1024; i++) {
            long long v = p[i];
            if (v < 0 || v >= NN) { ok = 0; break; }
        }
        g_is64 = ok;
    }
}

__device__ __forceinline__ int load_index(const void* p, long long i) {
    long long v = g_is64 ? ((const long long*)p)[i] : (long long)((const int*)p)[i];
    if (v < 0) v = 0;
    if (v >= NN) v = NN - 1;
    return (int)v;
}

__global__ void prep_kernel(const float* __restrict__ W1, const float* __restrict__ W2,
                            const float* __restrict__ W3, const float* __restrict__ W4) {
    int i = blockIdx.x * blockDim.x + threadIdx.x;
    int stride = gridDim.x * blockDim.x;
    for (; i < WB_HALF; i += stride) {
        float v; int l, n, k;
        if (i < 32768)       { l = i;          n = l >> 7; k = l & 127; v = W1[k * 256 + n]; }
        else if (i < 65536)  { l = i - 32768;  n = l >> 7; k = l & 127; v = W1[(k + 128) * 256 + n]; }
        else if (i < 131072) { l = i - 65536;  n = l >> 8; k = l & 255; v = W2[k * 256 + n]; }
        else if (i < 245760) { l = i - 131072; n = l / 448; k = l % 448; v = W3[k * 256 + n]; }
        else                 { l = i - 245760; n = l >> 8; k = l & 255; v = W4[k * 128 + n]; }
        __nv_bfloat16 h = __float2bfloat16(v);
        g_wb[i] = h;
        g_wb[WB_HALF + i] = __float2bfloat16(v - __bfloat162float(h));
    }
}

// ---------------------------------------------------------------------------
typedef wmma::fragment<wmma::accumulator, 16, 16, 16, float> FragC;

__device__ __forceinline__ void split4(float4 v, __nv_bfloat16* h, __nv_bfloat16* l) {
    float a[4] = {v.x, v.y, v.z, v.w};
#pragma unroll
    for (int i = 0; i < 4; i++) {
        __nv_bfloat16 hi = __float2bfloat16(a[i]);
        h[i] = hi;
        l[i] = __float2bfloat16(a[i] - __bfloat162float(hi));
    }
}
__device__ __forceinline__ void red_add4(float* p, float4 v) {
    asm volatile("red.global.add.v4.f32 [%0], {%1,%2,%3,%4};"
                 :: "l"(p), "f"(v.x), "f"(v.y), "f"(v.z), "f"(v.w) : "memory");
}
__device__ __forceinline__ void red_add1(float* p, float v) {
    asm volatile("red.global.add.f32 [%0], %1;" :: "l"(p), "f"(v) : "memory");
}
__device__ __forceinline__ void cpa16(void* d, const void* s) {
    uint32_t da = (uint32_t)__cvta_generic_to_shared(d);
    asm volatile("cp.async.cg.shared.global [%0], [%1], 16;" :: "r"(da), "l"(s) : "memory");
}
#define CP_COMMIT() asm volatile("cp.async.commit_group;" ::: "memory")
#define CP_WAIT0()  asm volatile("cp.async.wait_group 0;" ::: "memory")

// producer: B tile (128 N-rows x 64 K bf16 hi+lo) for chunk kc -> stage s
__device__ __forceinline__ void fill_B(char* stg, int wof, int K, int n0, int kc, int pt) {
    __nv_bfloat16* Bh = (__nv_bfloat16*)(stg + OFF_BH);
    __nv_bfloat16* Bl = (__nv_bfloat16*)(stg + OFF_BL);
    const __nv_bfloat16* sh = g_wb + wof + (size_t)n0 * K + kc;
    const __nv_bfloat16* sl = sh + WB_HALF;
    for (int i = pt; i < 1024; i += 128) {
        int n = i >> 3, kq = (i & 7) * 8;
        cpa16(Bh + n * LD + kq, sh + (size_t)n * K + kq);
        cpa16(Bl + n * LD + kq, sl + (size_t)n * K + kq);
    }
    CP_COMMIT();
    CP_WAIT0();
}

// consumer: one 64-deep K chunk on stage buffers; warp tile 64x64
__device__ __forceinline__ void warp_gemm64(const char* stg, FragC acc[4][4], int wm, int wn) {
    const __nv_bfloat16* Ah = (const __nv_bfloat16*)stg;
    const __nv_bfloat16* Al = (const __nv_bfloat16*)(stg + OFF_AL);
    const __nv_bfloat16* Bh = (const __nv_bfloat16*)(stg + OFF_BH);
    const __nv_bfloat16* Bl = (const __nv_bfloat16*)(stg + OFF_BL);
#pragma unroll
    for (int kk = 0; kk < 64; kk += 16) {
        wmma::fragment<wmma::matrix_a, 16, 16, 16, __nv_bfloat16, wmma::row_major> ah[4], al[4];
#pragma unroll
        for (int mi = 0; mi < 4; mi++) {
            wmma::load_matrix_sync(ah[mi], Ah + (wm * 64 + mi * 16) * LD + kk, LD);
            wmma::load_matrix_sync(al[mi], Al + (wm * 64 + mi * 16) * LD + kk, LD);
        }
#pragma unroll
        for (int ni = 0; ni < 4; ni++) {
            wmma::fragment<wmma::matrix_b, 16, 16, 16, __nv_bfloat16, wmma::col_major> bh, bl;
            wmma::load_matrix_sync(bh, Bh + (wn * 64 + ni * 16) * LD + kk, LD);
            wmma::load_matrix_sync(bl, Bl + (wn * 64 + ni * 16) * LD + kk, LD);
#pragma unroll
            for (int mi = 0; mi < 4; mi++) {
                wmma::mma_sync(acc[mi][ni], ah[mi], bh, acc[mi][ni]);
                wmma::mma_sync(acc[mi][ni], al[mi], bh, acc[mi][ni]);
                wmma::mma_sync(acc[mi][ni], ah[mi], bl, acc[mi][ni]);
            }
        }
    }
}

// warp-specialized pipelined GEMM. fillA(c, Ah, Al) runs on producer threads.
template<class FA>
__device__ __forceinline__ void run_ws(int C, FA&& fillA, char* smem,
                                       int wof, int K, int n0,
                                       FragC acc[4][4], int tid, int wm, int wn) {
    if (tid < 128) {                       // consumers: warps 0-3
        for (int c = 0; c < C; c++) {
            int s = c & 1;
            BAR_SYNC(1 + s);               // wait stage full
            warp_gemm64(smem + s * STG, acc, wm, wn);
            BAR_ARRIVE(3 + s);             // mark stage empty
        }
    } else {                               // producers: warps 4-7
        int pt = tid - 128;
        for (int c = 0; c < C; c++) {
            int s = c & 1;
            if (c >= 2) BAR_SYNC(3 + s);   // wait stage empty
            char* stg = smem + s * STG;
            fillA(c, (__nv_bfloat16*)stg, (__nv_bfloat16*)(stg + OFF_AL));
            fill_B(stg, wof, K, n0, c * 64, pt);
            BAR_ARRIVE(1 + s);             // mark stage full
        }
    }
    __syncthreads();
}

__device__ __forceinline__ void store_warpC(float* Cw, FragC acc[4][4]) {
#pragma unroll
    for (int mi = 0; mi < 4; mi++)
#pragma unroll
        for (int ni = 0; ni < 4; ni++)
            wmma::store_matrix_sync(Cw + (mi * 16) * 64 + ni * 16, acc[mi][ni], 64,
                                    wmma::mem_row_major);
}

#define GEMM_VARS() \
    extern __shared__ char smem[]; \
    int tid = threadIdx.x, w = tid >> 5, wm = w & 1, wn = w >> 1; \
    int pt = (tid >= 128) ? tid - 128 : 0; (void)pt; \
    int ny = blockIdx.y; (void)ny; \
    FragC acc[4][4]; \
    if (tid < 128) { \
        _Pragma("unroll") for (int mi = 0; mi < 4; mi++) \
        _Pragma("unroll") for (int ni = 0; ni < 4; ni++) wmma::fill_fragment(acc[mi][ni], 0.f); \
    }

// consumers dump C into smem, then ALL 256 threads run the epilogue loop
#define EPILOGUE_SETUP() \
    if (tid < 128) { float* Cw = (float*)smem + w * 4096; store_warpC(Cw, acc); } \
    __syncthreads(); \
    float* Call = (float*)smem;
// element mapping inside the 16384-elem C tile
#define EPI_IDX() \
    int wc = i >> 10, rem = i & 1023, r = rem >> 4, cc = (rem & 15) * 4; \
    int row = (wc & 1) * 64 + r; \
    int coll = (wc >> 1) * 64 + cc; \
    float4 cv = *(float4*)(Call + wc * 4096 + r * 64 + cc);

// ------------------------- p: P = x @ W1a + b1 (K=128) ---------------------
__global__ __launch_bounds__(256, 1) void p_kernel(const float* __restrict__ x,
                                                   const float* __restrict__ b1) {
    GEMM_VARS();
    int m0 = blockIdx.x * 128;
    auto fA = [&](int c, __nv_bfloat16* Ah, __nv_bfloat16* Al) {
        int kc = c * 64;
        for (int i = pt; i < 2048; i += 128) {
            int r = i >> 4, q = (i & 15) * 4;
            int n = m0 + r;
            float4 v = (n < NN) ? *(const float4*)&x[(size_t)n * 128 + kc + q]
                                : make_float4(0.f, 0.f, 0.f, 0.f);
            split4(v, Ah + r * LD + q, Al + r * LD + q);
        }
    };
    run_ws(2, fA, smem, WOF_W1A, 128, ny * 128, acc, tid, wm, wn);
    EPILOGUE_SETUP();
    for (int i = tid; i < 4096; i += 256) {
        EPI_IDX();
        int n = m0 + row;
        if (n < NN) {
            int col = ny * 128 + coll;
            cv.x += __ldg(&b1[col]);     cv.y += __ldg(&b1[col + 1]);
            cv.z += __ldg(&b1[col + 2]); cv.w += __ldg(&b1[col + 3]);
            *(float4*)(g_P + (size_t)n * HID + col) = cv;
        }
    }
}

// ------------------------- edge: red-scatter relu(ea@W1b + P[row]) ---------
__global__ __launch_bounds__(256, 1) void edge_kernel(const float* __restrict__ ea,
                                                      const void* __restrict__ ei) {
    GEMM_VARS();
    __shared__ int rs[128], cs[128];
    int e0 = blockIdx.x * 128;
    if (tid < 128) {
        rs[tid] = load_index(ei, e0 + tid);
        cs[tid] = load_index(ei, (long long)NE + e0 + tid);
    }
    __syncthreads();
    auto fA = [&](int c, __nv_bfloat16* Ah, __nv_bfloat16* Al) {
        int kc = c * 64;
        for (int i = pt; i < 2048; i += 128) {
            int r = i >> 4, q = (i & 15) * 4;
            float4 v = *(const float4*)&ea[(size_t)(e0 + r) * 128 + kc + q];
            split4(v, Ah + r * LD + q, Al + r * LD + q);
        }
    };
    run_ws(2, fA, smem, WOF_W1B, 128, ny * 128, acc, tid, wm, wn);
    EPILOGUE_SETUP();
    for (int i = tid; i < 4096; i += 256) {
        EPI_IDX();
        int col = ny * 128 + coll;
        float4 pv = *(const float4*)(g_P + (size_t)rs[row] * HID + col);
        float4 v;
        v.x = fmaxf(cv.x + pv.x, 0.f);
        v.y = fmaxf(cv.y + pv.y, 0.f);
        v.z = fmaxf(cv.z + pv.z, 0.f);
        v.w = fmaxf(cv.w + pv.w, 0.f);
        red_add4(g_agg + (size_t)cs[row] * HID + col, v);
    }
    if (ny == 0 && tid < 128) red_add1(&g_cnt[cs[tid]], 1.0f);
}

// ------------------------- agg2: (agg*rc) @ W2 + b2*ind (K=256) ------------
__global__ __launch_bounds__(256, 1) void agg2_kernel(const float* __restrict__ b2) {
    GEMM_VARS();
    __shared__ float rcs[128], inds[128];
    int m0 = blockIdx.x * 128;
    if (tid < 128) {
        int n = m0 + tid;
        float c = (n < NN) ? g_cnt[n] : 0.f;
        rcs[tid] = 1.0f / fmaxf(c, 1.0f);
        inds[tid] = (c > 0.f) ? 1.0f : 0.f;
    }
    __syncthreads();
    auto fA = [&](int c, __nv_bfloat16* Ah, __nv_bfloat16* Al) {
        int kc = c * 64;
        for (int i = pt; i < 2048; i += 128) {
            int r = i >> 4, q = (i & 15) * 4;
            int n = m0 + r;
            float4 v = make_float4(0.f, 0.f, 0.f, 0.f);
            if (n < NN) {
                v = *(const float4*)&g_agg[(size_t)n * HID + kc + q];
                float rc = rcs[r];
                v.x *= rc; v.y *= rc; v.z *= rc; v.w *= rc;
            }
            split4(v, Ah + r * LD + q, Al + r * LD + q);
        }
    };
    run_ws(4, fA, smem, WOF_W2, 256, ny * 128, acc, tid, wm, wn);
    EPILOGUE_SETUP();
    for (int i = tid; i < 4096; i += 256) {
        EPI_IDX();
        int n = m0 + row;
        if (n < NN) {
            int col = ny * 128 + coll;
            float ind = inds[row];
            cv.x += __ldg(&b2[col]) * ind;     cv.y += __ldg(&b2[col + 1]) * ind;
            cv.z += __ldg(&b2[col + 2]) * ind; cv.w += __ldg(&b2[col + 3]) * ind;
            *(float4*)(g_hagg + (size_t)n * HID + col) = cv;
        }
    }
}

// ------------------------- node1: t = relu([x||hagg||u]@W3+b3) -> g_P ------
__global__ __launch_bounds__(256, 1) void node1_kernel(const float* __restrict__ x,
                                                       const float* __restrict__ u,
                                                       const void* __restrict__ batch,
                                                       const float* __restrict__ b3) {
    GEMM_VARS();
    __shared__ int bts[128];
    int m0 = blockIdx.x * 128;
    if (tid < 128) {
        int n = m0 + tid;
        int b = (n < NN) ? load_index(batch, n) : 0;
        bts[tid] = (b < 64) ? b : 0;
    }
    __syncthreads();
    auto fA = [&](int c, __nv_bfloat16* Ah, __nv_bfloat16* Al) {
        int kc = c * 64;
        for (int i = pt; i < 2048; i += 128) {
            int r = i >> 4, q = (i & 15) * 4;
            int n = m0 + r;
            int k = kc + q;
            float4 v = make_float4(0.f, 0.f, 0.f, 0.f);
            if (n < NN) {
                if (k < 128)      v = *(const float4*)&x[(size_t)n * 128 + k];
                else if (k < 384) v = *(const float4*)&g_hagg[(size_t)n * HID + (k - 128)];
                else              v = *(const float4*)&u[bts[r] * 64 + (k - 384)];
            }
            split4(v, Ah + r * LD + q, Al + r * LD + q);
        }
    };
    run_ws(7, fA, smem, WOF_W3, 448, ny * 128, acc, tid, wm, wn);
    EPILOGUE_SETUP();
    for (int i = tid; i < 4096; i += 256) {
        EPI_IDX();
        int n = m0 + row;
        if (n < NN) {
            int col = ny * 128 + coll;
            cv.x = fmaxf(cv.x + __ldg(&b3[col]), 0.f);
            cv.y = fmaxf(cv.y + __ldg(&b3[col + 1]), 0.f);
            cv.z = fmaxf(cv.z + __ldg(&b3[col + 2]), 0.f);
            cv.w = fmaxf(cv.w + __ldg(&b3[col + 3]), 0.f);
            *(float4*)(g_P + (size_t)n * HID + col) = cv;
        }
    }
}

// ------------------------- node2: out = t @ W4 + b4 (K=256, N=128) ---------
__global__ __launch_bounds__(256, 1) void node2_kernel(const float* __restrict__ b4,
                                                       float* __restrict__ out) {
    GEMM_VARS();
    int m0 = blockIdx.x * 128;
    auto fA = [&](int c, __nv_bfloat16* Ah, __nv_bfloat16* Al) {
        int kc = c * 64;
        for (int i = pt; i < 2048; i += 128) {
            int r = i >> 4, q = (i & 15) * 4;
            int n = m0 + r;
            float4 v = (n < NN) ? *(const float4*)&g_P[(size_t)n * HID + kc + q]
                                : make_float4(0.f, 0.f, 0.f, 0.f);
            split4(v, Ah + r * LD + q, Al + r * LD + q);
        }
    };
    run_ws(4, fA, smem, WOF_W4, 256, 0, acc, tid, wm, wn);
    EPILOGUE_SETUP();
    for (int i = tid; i < 4096; i += 256) {
        EPI_IDX();
        int n = m0 + row;
        if (n < NN) {
            cv.x += __ldg(&b4[coll]);     cv.y += __ldg(&b4[coll + 1]);
            cv.z += __ldg(&b4[coll + 2]); cv.w += __ldg(&b4[coll + 3]);
            *(float4*)(out + (size_t)n * 128 + coll) = cv;
        }
    }
}

// ---------------------------------------------------------------------------
extern "C" void kernel_launch(void* const* d_in, const int* in_sizes, int n_in,
                              void* d_out, int out_size) {
    const float* x     = (const float*)d_in[0];
    const void*  ei    = d_in[1];
    const float* ea    = (const float*)d_in[2];
    const float* u     = (const float*)d_in[3];
    const void*  batch = d_in[4];
    const float* W1    = (const float*)d_in[5];
    const float* b1    = (const float*)d_in[6];
    const float* W2    = (const float*)d_in[7];
    const float* b2    = (const float*)d_in[8];
    const float* W3    = (const float*)d_in[9];
    const float* b3    = (const float*)d_in[10];
    const float* W4    = (const float*)d_in[11];
    const float* b4    = (const float*)d_in[12];
    float* out = (float*)d_out;

    static int attr_done = 0;
    if (!attr_done) {
        cudaFuncSetAttribute(p_kernel,     cudaFuncAttributeMaxDynamicSharedMemorySize, SMEM_TOTAL);
        cudaFuncSetAttribute(edge_kernel,  cudaFuncAttributeMaxDynamicSharedMemorySize, SMEM_TOTAL);
        cudaFuncSetAttribute(agg2_kernel,  cudaFuncAttributeMaxDynamicSharedMemorySize, SMEM_TOTAL);
        cudaFuncSetAttribute(node1_kernel, cudaFuncAttributeMaxDynamicSharedMemorySize, SMEM_TOTAL);
        cudaFuncSetAttribute(node2_kernel, cudaFuncAttributeMaxDynamicSharedMemorySize, SMEM_TOTAL);
        attr_done = 1;
    }

    int nblk = (NN + 127) / 128;
    dim3 g2(nblk, 2), ge(NE / 128, 2), g1(nblk, 1);
    zero_kernel<<<2048, 256>>>(ei);
    prep_kernel<<<512, 256>>>(W1, W2, W3, W4);
    p_kernel<<<g2, 256, SMEM_TOTAL>>>(x, b1);
    edge_kernel<<<ge, 256, SMEM_TOTAL>>>(ea, ei);
    agg2_kernel<<<g2, 256, SMEM_TOTAL>>>(b2);
    node1_kernel<<<g2, 256, SMEM_TOTAL>>>(x, u, batch, b3);
    node2_kernel<<<g1, 256, SMEM_TOTAL>>>(b4, out);
}

// round 15
// speedup vs baseline: 1.5550x; 1.5550x over previous
#include <cuda_runtime.h>
#include <cuda_bf16.h>
#include <mma.h>
#include <cstdint>

using namespace nvcuda;

#define NN   50000
#define NE   640000
#define HID  256
#define LDA  40    // smem leading dim (elems) for 32-deep chunks (80B, conflict-free)
#define LDB  40

#define WOF_W1A 0
#define WOF_W1B 32768
#define WOF_W2  65536
#define WOF_W3  131072
#define WOF_W4  245760
#define WB_HALF 278528

__device__ __align__(16) __nv_bfloat16 g_wb[2 * WB_HALF];
__device__ __align__(16) __nv_bfloat16 g_eah[(size_t)NE * 128], g_eal[(size_t)NE * 128];
__device__ __align__(16) __nv_bfloat16 g_xh[NN * 128], g_xl[NN * 128];
__device__ __align__(16) __nv_bfloat16 g_ah[NN * 256], g_al[NN * 256];   // agg split
__device__ __align__(16) __nv_bfloat16 g_hh[NN * 256], g_hl[NN * 256];   // hagg split
__device__ __align__(16) __nv_bfloat16 g_th[NN * 256], g_tl[NN * 256];   // t split
__device__ __align__(16) __nv_bfloat16 g_uh[64 * 64], g_ul[64 * 64];
__device__ float g_P[NN * HID];
__device__ float g_agg[NN * HID];
__device__ float g_cnt[NN];
__device__ int   g_is64;

// per-stage smem (bytes): Ah 0 | Al 10240 | Bh 20480 | Bl 30720 ; 2 stages
#define OFF_AL 10240
#define OFF_BH 20480
#define OFF_BL 30720
#define STG    40960
#define SMEM_TOTAL 81920

// ---------------------------------------------------------------------------
__global__ void zero_kernel(const void* ei_raw) {
    int idx = blockIdx.x * blockDim.x + threadIdx.x;
    int stride = gridDim.x * blockDim.x;
    for (int i = idx; i < NN * HID; i += stride) g_agg[i] = 0.f;
    for (int i = idx; i < NN; i += stride) g_cnt[i] = 0.f;
    if (idx == 0) {
        const long long* p = (const long long*)ei_raw;
        int ok = 1;
        for (int i = 0; i < 1024; i++) {
            long long v = p[i];
            if (v < 0 || v >= NN) { ok = 0; break; }
        }
        g_is64 = ok;
    }
}

__device__ __forceinline__ int load_index(const void* p, long long i) {
    long long v = g_is64 ? ((const long long*)p)[i] : (long long)((const int*)p)[i];
    if (v < 0) v = 0;
    if (v >= NN) v = NN - 1;
    return (int)v;
}

__global__ void prep_kernel(const float* __restrict__ W1, const float* __restrict__ W2,
                            const float* __restrict__ W3, const float* __restrict__ W4) {
    int i = blockIdx.x * blockDim.x + threadIdx.x;
    int stride = gridDim.x * blockDim.x;
    for (; i < WB_HALF; i += stride) {
        float v; int l, n, k;
        if (i < 32768)       { l = i;          n = l >> 7; k = l & 127; v = W1[k * 256 + n]; }
        else if (i < 65536)  { l = i - 32768;  n = l >> 7; k = l & 127; v = W1[(k + 128) * 256 + n]; }
        else if (i < 131072) { l = i - 65536;  n = l >> 8; k = l & 255; v = W2[k * 256 + n]; }
        else if (i < 245760) { l = i - 131072; n = l / 448; k = l % 448; v = W3[k * 256 + n]; }
        else                 { l = i - 245760; n = l >> 8; k = l & 255; v = W4[k * 128 + n]; }
        __nv_bfloat16 h = __float2bfloat16(v);
        g_wb[i] = h;
        g_wb[WB_HALF + i] = __float2bfloat16(v - __bfloat162float(h));
    }
}

// pack 4 fp32 -> hi/lo bf16x4 (uint2 each)
__device__ __forceinline__ void split_store4(__nv_bfloat16* hp, __nv_bfloat16* lp, float4 v) {
    float a[4] = {v.x, v.y, v.z, v.w};
    uint2 uh, ul;
    uint32_t hw[4], lw[4];
#pragma unroll
    for (int i = 0; i < 4; i++) {
        __nv_bfloat16 h = __float2bfloat16(a[i]);
        hw[i] = (uint32_t)__bfloat16_as_ushort(h);
        lw[i] = (uint32_t)__bfloat16_as_ushort(__float2bfloat16(a[i] - __bfloat162float(h)));
    }
    uh.x = hw[0] | (hw[1] << 16); uh.y = hw[2] | (hw[3] << 16);
    ul.x = lw[0] | (lw[1] << 16); ul.y = lw[2] | (lw[3] << 16);
    *(uint2*)hp = uh;
    *(uint2*)lp = ul;
}

// split ea, x, u into bf16 hi/lo
__global__ void split_in(const float* __restrict__ ea, const float* __restrict__ x,
                         const float* __restrict__ u) {
    long long idx = (long long)(blockIdx.x * blockDim.x + threadIdx.x) * 4;
    long long stride = (long long)gridDim.x * blockDim.x * 4;
    const long long EAE = (long long)NE * 128;
    for (long long i = idx; i < EAE; i += stride)
        split_store4(g_eah + i, g_eal + i, *(const float4*)(ea + i));
    for (long long i = idx; i < (long long)NN * 128; i += stride)
        split_store4(g_xh + i, g_xl + i, *(const float4*)(x + i));
    for (long long i = idx; i < 64 * 64; i += stride)
        split_store4(g_uh + i, g_ul + i, *(const float4*)(u + i));
}

__global__ void split_agg(void) {
    long long idx = (long long)(blockIdx.x * blockDim.x + threadIdx.x) * 4;
    long long stride = (long long)gridDim.x * blockDim.x * 4;
    for (long long i = idx; i < (long long)NN * 256; i += stride)
        split_store4(g_ah + i, g_al + i, *(const float4*)(g_agg + i));
}

// ---------------------------------------------------------------------------
typedef wmma::fragment<wmma::accumulator, 16, 16, 16, float> FragC;

__device__ __forceinline__ void red_add4(float* p, float4 v) {
    asm volatile("red.global.add.v4.f32 [%0], {%1,%2,%3,%4};"
                 :: "l"(p), "f"(v.x), "f"(v.y), "f"(v.z), "f"(v.w) : "memory");
}
__device__ __forceinline__ void red_add1(float* p, float v) {
    asm volatile("red.global.add.f32 [%0], %1;" :: "l"(p), "f"(v) : "memory");
}
__device__ __forceinline__ void cpa16(void* d, const void* s) {
    uint32_t da = (uint32_t)__cvta_generic_to_shared(d);
    asm volatile("cp.async.cg.shared.global [%0], [%1], 16;" :: "r"(da), "l"(s) : "memory");
}
__device__ __forceinline__ void cpa16p(void* d, const void* s, bool pred) {
    uint32_t da = (uint32_t)__cvta_generic_to_shared(d);
    int sz = pred ? 16 : 0;
    asm volatile("cp.async.cg.shared.global [%0], [%1], 16, %2;" :: "r"(da), "l"(s), "r"(sz) : "memory");
}
#define CP_COMMIT() asm volatile("cp.async.commit_group;" ::: "memory")
#define CP_WAIT1()  asm volatile("cp.async.wait_group 1;" ::: "memory")
#define CP_WAIT0()  asm volatile("cp.async.wait_group 0;" ::: "memory")

// one 32-deep K chunk: warp tile 64x64, 3-term bf16 split
__device__ __forceinline__ void warp_gemm32(const char* stg, FragC acc[4][4], int wm, int wn) {
    const __nv_bfloat16* Ah = (const __nv_bfloat16*)stg;
    const __nv_bfloat16* Al = (const __nv_bfloat16*)(stg + OFF_AL);
    const __nv_bfloat16* Bh = (const __nv_bfloat16*)(stg + OFF_BH);
    const __nv_bfloat16* Bl = (const __nv_bfloat16*)(stg + OFF_BL);
#pragma unroll
    for (int kk = 0; kk < 32; kk += 16) {
        wmma::fragment<wmma::matrix_a, 16, 16, 16, __nv_bfloat16, wmma::row_major> ah[4], al[4];
#pragma unroll
        for (int mi = 0; mi < 4; mi++) {
            wmma::load_matrix_sync(ah[mi], Ah + (wm * 64 + mi * 16) * LDA + kk, LDA);
            wmma::load_matrix_sync(al[mi], Al + (wm * 64 + mi * 16) * LDA + kk, LDA);
        }
#pragma unroll
        for (int ni = 0; ni < 4; ni++) {
            wmma::fragment<wmma::matrix_b, 16, 16, 16, __nv_bfloat16, wmma::col_major> bh, bl;
            wmma::load_matrix_sync(bh, Bh + (wn * 64 + ni * 16) * LDB + kk, LDB);
            wmma::load_matrix_sync(bl, Bl + (wn * 64 + ni * 16) * LDB + kk, LDB);
#pragma unroll
            for (int mi = 0; mi < 4; mi++) {
                wmma::mma_sync(acc[mi][ni], ah[mi], bh, acc[mi][ni]);
                wmma::mma_sync(acc[mi][ni], al[mi], bh, acc[mi][ni]);
                wmma::mma_sync(acc[mi][ni], ah[mi], bl, acc[mi][ni]);
            }
        }
    }
}

// double-buffered (A and B) pipeline; fA/fB issue cp.async for chunk c into stage
template<class FA, class FB>
__device__ __forceinline__ void run_pipe(int C, FA&& fA, FB&& fB, char* smem,
                                         FragC acc[4][4], int wm, int wn) {
    fA(0, smem); fB(0, smem); CP_COMMIT();
    if (C > 1) { fA(1, smem + STG); fB(1, smem + STG); CP_COMMIT(); }
    for (int c = 0; c < C; c++) {
        if (c + 2 < C) CP_WAIT1(); else CP_WAIT0();
        __syncthreads();
        warp_gemm32(smem + (c & 1) * STG, acc, wm, wn);
        __syncthreads();
        if (c + 2 < C) {
            char* stg = smem + (c & 1) * STG;
            fA(c + 2, stg); fB(c + 2, stg); CP_COMMIT();
        }
    }
}

__device__ __forceinline__ void store_warpC(float* Cw, FragC acc[4][4]) {
#pragma unroll
    for (int mi = 0; mi < 4; mi++)
#pragma unroll
        for (int ni = 0; ni < 4; ni++)
            wmma::store_matrix_sync(Cw + (mi * 16) * 64 + ni * 16, acc[mi][ni], 64,
                                    wmma::mem_row_major);
}

#define GEMM_VARS() \
    extern __shared__ char smem[]; \
    int tid = threadIdx.x, lane = tid & 31, w = tid >> 5, wm = w & 1, wn = w >> 1; \
    int ny = blockIdx.y; (void)ny; \
    FragC acc[4][4]; \
    _Pragma("unroll") for (int mi = 0; mi < 4; mi++) \
    _Pragma("unroll") for (int ni = 0; ni < 4; ni++) wmma::fill_fragment(acc[mi][ni], 0.f);

// B filler: 128 N-rows x 32 K (hi+lo) for chunk c
#define MAKE_FB(wof, K, n0) \
    auto fB = [&](int c, char* stg) { \
        const __nv_bfloat16* sh = g_wb + (wof) + (size_t)(n0) * (K) + c * 32; \
        const __nv_bfloat16* sl = sh + WB_HALF; \
        __nv_bfloat16* Bh = (__nv_bfloat16*)(stg + OFF_BH); \
        __nv_bfloat16* Bl = (__nv_bfloat16*)(stg + OFF_BL); \
        for (int i = tid; i < 512; i += 128) { \
            int n = i >> 2, kq = (i & 3) * 8; \
            cpa16(Bh + n * LDB + kq, sh + (size_t)n * (K) + kq); \
            cpa16(Bl + n * LDB + kq, sl + (size_t)n * (K) + kq); \
        } \
    };

#define EPILOGUE_SETUP() \
    float* Cw = (float*)smem + w * 4096; \
    store_warpC(Cw, acc); \
    __syncwarp();

// ------------------------- p: P = x @ W1a + b1 (K=128) ---------------------
__global__ __launch_bounds__(128, 2) void p_kernel(const float* __restrict__ b1) {
    GEMM_VARS();
    int m0 = blockIdx.x * 128;
    auto fA = [&](int c, char* stg) {
        int kc = c * 32;
        __nv_bfloat16* Ah = (__nv_bfloat16*)stg;
        __nv_bfloat16* Al = (__nv_bfloat16*)(stg + OFF_AL);
        for (int i = tid; i < 512; i += 128) {
            int r = i >> 2, q = (i & 3) * 8;
            int n = m0 + r;
            cpa16p(Ah + r * LDA + q, g_xh + (size_t)n * 128 + kc + q, n < NN);
            cpa16p(Al + r * LDA + q, g_xl + (size_t)n * 128 + kc + q, n < NN);
        }
    };
    MAKE_FB(WOF_W1A, 128, ny * 128);
    run_pipe(4, fA, fB, smem, acc, wm, wn);
    EPILOGUE_SETUP();
    for (int i2 = lane; i2 < 1024; i2 += 32) {
        int r = i2 >> 4, c = (i2 & 15) * 4;
        int n = m0 + wm * 64 + r;
        if (n < NN) {
            int col = ny * 128 + wn * 64 + c;
            float4 cv = *(float4*)(Cw + r * 64 + c);
            cv.x += __ldg(&b1[col]);     cv.y += __ldg(&b1[col + 1]);
            cv.z += __ldg(&b1[col + 2]); cv.w += __ldg(&b1[col + 3]);
            *(float4*)(g_P + (size_t)n * HID + col) = cv;
        }
    }
}

// ------------------------- edge: red-scatter relu(ea@W1b + P[row]) ---------
__global__ __launch_bounds__(128, 2) void edge_kernel(const void* __restrict__ ei) {
    GEMM_VARS();
    __shared__ int rs[128], cs[128];
    int e0 = blockIdx.x * 128;
    rs[tid] = load_index(ei, e0 + tid);
    cs[tid] = load_index(ei, (long long)NE + e0 + tid);
    auto fA = [&](int c, char* stg) {
        int kc = c * 32;
        __nv_bfloat16* Ah = (__nv_bfloat16*)stg;
        __nv_bfloat16* Al = (__nv_bfloat16*)(stg + OFF_AL);
        for (int i = tid; i < 512; i += 128) {
            int r = i >> 2, q = (i & 3) * 8;
            size_t off = (size_t)(e0 + r) * 128 + kc + q;
            cpa16(Ah + r * LDA + q, g_eah + off);
            cpa16(Al + r * LDA + q, g_eal + off);
        }
    };
    MAKE_FB(WOF_W1B, 128, ny * 128);
    run_pipe(4, fA, fB, smem, acc, wm, wn);
    EPILOGUE_SETUP();
    for (int i2 = lane; i2 < 1024; i2 += 32) {
        int r = i2 >> 4, c = (i2 & 15) * 4;
        int lr = wm * 64 + r;
        int col = ny * 128 + wn * 64 + c;
        float4 cv = *(float4*)(Cw + r * 64 + c);
        float4 pv = *(const float4*)(g_P + (size_t)rs[lr] * HID + col);
        float4 v;
        v.x = fmaxf(cv.x + pv.x, 0.f);
        v.y = fmaxf(cv.y + pv.y, 0.f);
        v.z = fmaxf(cv.z + pv.z, 0.f);
        v.w = fmaxf(cv.w + pv.w, 0.f);
        red_add4(g_agg + (size_t)cs[lr] * HID + col, v);
    }
    if (ny == 0) red_add1(&g_cnt[cs[tid]], 1.0f);
}

// ------------------------- agg2: rc*(agg@W2) + b2*ind -> hagg hi/lo --------
__global__ __launch_bounds__(128, 2) void agg2_kernel(const float* __restrict__ b2) {
    GEMM_VARS();
    __shared__ float rcs[128], inds[128];
    int m0 = blockIdx.x * 128;
    {
        int n = m0 + tid;
        float c = (n < NN) ? g_cnt[n] : 0.f;
        rcs[tid] = 1.0f / fmaxf(c, 1.0f);
        inds[tid] = (c > 0.f) ? 1.0f : 0.f;
    }
    auto fA = [&](int c, char* stg) {
        int kc = c * 32;
        __nv_bfloat16* Ah = (__nv_bfloat16*)stg;
        __nv_bfloat16* Al = (__nv_bfloat16*)(stg + OFF_AL);
        for (int i = tid; i < 512; i += 128) {
            int r = i >> 2, q = (i & 3) * 8;
            int n = m0 + r;
            cpa16p(Ah + r * LDA + q, g_ah + (size_t)n * 256 + kc + q, n < NN);
            cpa16p(Al + r * LDA + q, g_al + (size_t)n * 256 + kc + q, n < NN);
        }
    };
    MAKE_FB(WOF_W2, 256, ny * 128);
    run_pipe(8, fA, fB, smem, acc, wm, wn);
    EPILOGUE_SETUP();
    for (int i2 = lane; i2 < 1024; i2 += 32) {
        int r = i2 >> 4, c = (i2 & 15) * 4;
        int n = m0 + wm * 64 + r;
        if (n < NN) {
            int col = ny * 128 + wn * 64 + c;
            float rc = rcs[wm * 64 + r], ind = inds[wm * 64 + r];
            float4 cv = *(float4*)(Cw + r * 64 + c);
            cv.x = cv.x * rc + __ldg(&b2[col]) * ind;
            cv.y = cv.y * rc + __ldg(&b2[col + 1]) * ind;
            cv.z = cv.z * rc + __ldg(&b2[col + 2]) * ind;
            cv.w = cv.w * rc + __ldg(&b2[col + 3]) * ind;
            split_store4(g_hh + (size_t)n * 256 + col, g_hl + (size_t)n * 256 + col, cv);
        }
    }
}

// ------------------------- node1: t = relu([x||hagg||u]@W3+b3) -> t hi/lo --
__global__ __launch_bounds__(128, 2) void node1_kernel(const void* __restrict__ batch,
                                                       const float* __restrict__ b3) {
    GEMM_VARS();
    __shared__ int bts[128];
    int m0 = blockIdx.x * 128;
    {
        int n = m0 + tid;
        int b = (n < NN) ? load_index(batch, n) : 0;
        bts[tid] = (b < 64) ? b : 0;
    }
    __syncthreads();
    auto fA = [&](int c, char* stg) {
        int kc = c * 32;
        __nv_bfloat16* Ah = (__nv_bfloat16*)stg;
        __nv_bfloat16* Al = (__nv_bfloat16*)(stg + OFF_AL);
        for (int i = tid; i < 512; i += 128) {
            int r = i >> 2, q = (i & 3) * 8;
            int n = m0 + r;
            int k = kc + q;
            const __nv_bfloat16 *sh, *sl;
            if (k < 128)      { sh = g_xh + (size_t)n * 128 + k;          sl = g_xl + (size_t)n * 128 + k; }
            else if (k < 384) { sh = g_hh + (size_t)n * 256 + (k - 128);  sl = g_hl + (size_t)n * 256 + (k - 128); }
            else              { sh = g_uh + bts[r] * 64 + (k - 384);      sl = g_ul + bts[r] * 64 + (k - 384); }
            cpa16p(Ah + r * LDA + q, sh, n < NN);
            cpa16p(Al + r * LDA + q, sl, n < NN);
        }
    };
    MAKE_FB(WOF_W3, 448, ny * 128);
    run_pipe(14, fA, fB, smem, acc, wm, wn);
    EPILOGUE_SETUP();
    for (int i2 = lane; i2 < 1024; i2 += 32) {
        int r = i2 >> 4, c = (i2 & 15) * 4;
        int n = m0 + wm * 64 + r;
        if (n < NN) {
            int col = ny * 128 + wn * 64 + c;
            float4 cv = *(float4*)(Cw + r * 64 + c);
            cv.x = fmaxf(cv.x + __ldg(&b3[col]), 0.f);
            cv.y = fmaxf(cv.y + __ldg(&b3[col + 1]), 0.f);
            cv.z = fmaxf(cv.z + __ldg(&b3[col + 2]), 0.f);
            cv.w = fmaxf(cv.w + __ldg(&b3[col + 3]), 0.f);
            split_store4(g_th + (size_t)n * 256 + col, g_tl + (size_t)n * 256 + col, cv);
        }
    }
}

// ------------------------- node2: out = t @ W4 + b4 (K=256, N=128) ---------
__global__ __launch_bounds__(128, 2) void node2_kernel(const float* __restrict__ b4,
                                                       float* __restrict__ out) {
    GEMM_VARS();
    int m0 = blockIdx.x * 128;
    auto fA = [&](int c, char* stg) {
        int kc = c * 32;
        __nv_bfloat16* Ah = (__nv_bfloat16*)stg;
        __nv_bfloat16* Al = (__nv_bfloat16*)(stg + OFF_AL);
        for (int i = tid; i < 512; i += 128) {
            int r = i >> 2, q = (i & 3) * 8;
            int n = m0 + r;
            cpa16p(Ah + r * LDA + q, g_th + (size_t)n * 256 + kc + q, n < NN);
            cpa16p(Al + r * LDA + q, g_tl + (size_t)n * 256 + kc + q, n < NN);
        }
    };
    MAKE_FB(WOF_W4, 256, 0);
    run_pipe(8, fA, fB, smem, acc, wm, wn);
    EPILOGUE_SETUP();
    for (int i2 = lane; i2 < 1024; i2 += 32) {
        int r = i2 >> 4, c = (i2 & 15) * 4;
        int n = m0 + wm * 64 + r;
        if (n < NN) {
            int col = wn * 64 + c;
            float4 cv = *(float4*)(Cw + r * 64 + c);
            cv.x += __ldg(&b4[col]);     cv.y += __ldg(&b4[col + 1]);
            cv.z += __ldg(&b4[col + 2]); cv.w += __ldg(&b4[col + 3]);
            *(float4*)(out + (size_t)n * 128 + col) = cv;
        }
    }
}

// ---------------------------------------------------------------------------
extern "C" void kernel_launch(void* const* d_in, const int* in_sizes, int n_in,
                              void* d_out, int out_size) {
    const float* x     = (const float*)d_in[0];
    const void*  ei    = d_in[1];
    const float* ea    = (const float*)d_in[2];
    const float* u     = (const float*)d_in[3];
    const void*  batch = d_in[4];
    const float* W1    = (const float*)d_in[5];
    const float* b1    = (const float*)d_in[6];
    const float* W2    = (const float*)d_in[7];
    const float* b2    = (const float*)d_in[8];
    const float* W3    = (const float*)d_in[9];
    const float* b3    = (const float*)d_in[10];
    const float* W4    = (const float*)d_in[11];
    const float* b4    = (const float*)d_in[12];
    float* out = (float*)d_out;

    static int attr_done = 0;
    if (!attr_done) {
        cudaFuncSetAttribute(p_kernel,     cudaFuncAttributeMaxDynamicSharedMemorySize, SMEM_TOTAL);
        cudaFuncSetAttribute(edge_kernel,  cudaFuncAttributeMaxDynamicSharedMemorySize, SMEM_TOTAL);
        cudaFuncSetAttribute(agg2_kernel,  cudaFuncAttributeMaxDynamicSharedMemorySize, SMEM_TOTAL);
        cudaFuncSetAttribute(node1_kernel, cudaFuncAttributeMaxDynamicSharedMemorySize, SMEM_TOTAL);
        cudaFuncSetAttribute(node2_kernel, cudaFuncAttributeMaxDynamicSharedMemorySize, SMEM_TOTAL);
        attr_done = 1;
    }

    int nblk = (NN + 127) / 128;
    dim3 g2(nblk, 2), ge(NE / 128, 2), g1(nblk, 1);
    zero_kernel<<<2048, 256>>>(ei);
    prep_kernel<<<512, 256>>>(W1, W2, W3, W4);
    split_in<<<2048, 256>>>(ea, x, u);
    p_kernel<<<g2, 128, SMEM_TOTAL>>>(b1);
    edge_kernel<<<ge, 128, SMEM_TOTAL>>>(ei);
    split_agg<<<1024, 256>>>();
    agg2_kernel<<<g2, 128, SMEM_TOTAL>>>(b2);
    node1_kernel<<<g2, 128, SMEM_TOTAL>>>(batch, b3);
    node2_kernel<<<g1, 128, SMEM_TOTAL>>>(b4, out);
}

// round 16
// speedup vs baseline: 1.5666x; 1.0075x over previous
#include <cuda_runtime.h>
#include <cuda_bf16.h>
#include <mma.h>
#include <cstdint>

using namespace nvcuda;

#define NN   50000
#define NE   640000
#define HID  256
#define LDA  40    // smem leading dim for pipelined (K=32 chunk) A tiles
#define LDB  40
#define LDAF 136   // leading dim for fully-resident K=128 A (272B stride, conflict-free)

#define WOF_W1A 0
#define WOF_W1B 32768
#define WOF_W2  65536
#define WOF_W3  131072
#define WOF_W4  245760
#define WB_HALF 278528

__device__ __align__(16) __nv_bfloat16 g_wb[2 * WB_HALF];
__device__ __align__(16) __nv_bfloat16 g_eah[(size_t)NE * 128], g_eal[(size_t)NE * 128];
__device__ __align__(16) __nv_bfloat16 g_xh[NN * 128], g_xl[NN * 128];
__device__ __align__(16) __nv_bfloat16 g_ah[NN * 256], g_al[NN * 256];   // agg split
__device__ __align__(16) __nv_bfloat16 g_hh[NN * 256], g_hl[NN * 256];   // hagg split
__device__ __align__(16) __nv_bfloat16 g_th[NN * 256], g_tl[NN * 256];   // t split
__device__ __align__(16) __nv_bfloat16 g_uh[64 * 64], g_ul[64 * 64];
__device__ float g_P[NN * HID];
__device__ float g_agg[NN * HID];
__device__ float g_cnt[NN];
__device__ int   g_is64;

// pipelined-kernel smem (agg2/node1/node2): Ah|Al|Bh|Bl per stage, 2 stages
#define OFF_AL 10240
#define OFF_BH 20480
#define OFF_BL 30720
#define STG    40960
#define SMEM_PIPE 81920

// A-resident smem (p/edge): Ah[0,34816) Al[34816,69632) B stages at 69632
#define OFF_ALR 34816
#define OFF_B   69632
#define STGB    20480      // per stage: Bh 10240 + Bl 10240
#define SMEM_ARES 110592

// ---------------------------------------------------------------------------
__global__ void zero_kernel(const void* ei_raw) {
    int idx = blockIdx.x * blockDim.x + threadIdx.x;
    int stride = gridDim.x * blockDim.x;
    for (int i = idx; i < NN * HID; i += stride) g_agg[i] = 0.f;
    for (int i = idx; i < NN; i += stride) g_cnt[i] = 0.f;
    if (idx == 0) {
        const long long* p = (const long long*)ei_raw;
        int ok = 1;
        for (int i = 0; i < 1024; i++) {
            long long v = p[i];
            if (v < 0 || v >= NN) { ok = 0; break; }
        }
        g_is64 = ok;
    }
}

__device__ __forceinline__ int load_index(const void* p, long long i) {
    long long v = g_is64 ? ((const long long*)p)[i] : (long long)((const int*)p)[i];
    if (v < 0) v = 0;
    if (v >= NN) v = NN - 1;
    return (int)v;
}

__global__ void prep_kernel(const float* __restrict__ W1, const float* __restrict__ W2,
                            const float* __restrict__ W3, const float* __restrict__ W4) {
    int i = blockIdx.x * blockDim.x + threadIdx.x;
    int stride = gridDim.x * blockDim.x;
    for (; i < WB_HALF; i += stride) {
        float v; int l, n, k;
        if (i < 32768)       { l = i;          n = l >> 7; k = l & 127; v = W1[k * 256 + n]; }
        else if (i < 65536)  { l = i - 32768;  n = l >> 7; k = l & 127; v = W1[(k + 128) * 256 + n]; }
        else if (i < 131072) { l = i - 65536;  n = l >> 8; k = l & 255; v = W2[k * 256 + n]; }
        else if (i < 245760) { l = i - 131072; n = l / 448; k = l % 448; v = W3[k * 256 + n]; }
        else                 { l = i - 245760; n = l >> 8; k = l & 255; v = W4[k * 128 + n]; }
        __nv_bfloat16 h = __float2bfloat16(v);
        g_wb[i] = h;
        g_wb[WB_HALF + i] = __float2bfloat16(v - __bfloat162float(h));
    }
}

// pack 4 fp32 -> hi/lo bf16x4
__device__ __forceinline__ void split_store4(__nv_bfloat16* hp, __nv_bfloat16* lp, float4 v) {
    float a[4] = {v.x, v.y, v.z, v.w};
    uint2 uh, ul;
    uint32_t hw[4], lw[4];
#pragma unroll
    for (int i = 0; i < 4; i++) {
        __nv_bfloat16 h = __float2bfloat16(a[i]);
        hw[i] = (uint32_t)__bfloat16_as_ushort(h);
        lw[i] = (uint32_t)__bfloat16_as_ushort(__float2bfloat16(a[i] - __bfloat162float(h)));
    }
    uh.x = hw[0] | (hw[1] << 16); uh.y = hw[2] | (hw[3] << 16);
    ul.x = lw[0] | (lw[1] << 16); ul.y = lw[2] | (lw[3] << 16);
    *(uint2*)hp = uh;
    *(uint2*)lp = ul;
}

__global__ void split_in(const float* __restrict__ ea, const float* __restrict__ x,
                         const float* __restrict__ u) {
    long long idx = (long long)(blockIdx.x * blockDim.x + threadIdx.x) * 4;
    long long stride = (long long)gridDim.x * blockDim.x * 4;
    const long long EAE = (long long)NE * 128;
    for (long long i = idx; i < EAE; i += stride)
        split_store4(g_eah + i, g_eal + i, *(const float4*)(ea + i));
    for (long long i = idx; i < (long long)NN * 128; i += stride)
        split_store4(g_xh + i, g_xl + i, *(const float4*)(x + i));
    for (long long i = idx; i < 64 * 64; i += stride)
        split_store4(g_uh + i, g_ul + i, *(const float4*)(u + i));
}

__global__ void split_agg(void) {
    long long idx = (long long)(blockIdx.x * blockDim.x + threadIdx.x) * 4;
    long long stride = (long long)gridDim.x * blockDim.x * 4;
    for (long long i = idx; i < (long long)NN * 256; i += stride)
        split_store4(g_ah + i, g_al + i, *(const float4*)(g_agg + i));
}

// ---------------------------------------------------------------------------
typedef wmma::fragment<wmma::accumulator, 16, 16, 16, float> FragC;

__device__ __forceinline__ void red_add4(float* p, float4 v) {
    asm volatile("red.global.add.v4.f32 [%0], {%1,%2,%3,%4};"
                 :: "l"(p), "f"(v.x), "f"(v.y), "f"(v.z), "f"(v.w) : "memory");
}
__device__ __forceinline__ void red_add1(float* p, float v) {
    asm volatile("red.global.add.f32 [%0], %1;" :: "l"(p), "f"(v) : "memory");
}
__device__ __forceinline__ void cpa16(void* d, const void* s) {
    uint32_t da = (uint32_t)__cvta_generic_to_shared(d);
    asm volatile("cp.async.cg.shared.global [%0], [%1], 16;" :: "r"(da), "l"(s) : "memory");
}
__device__ __forceinline__ void cpa16p(void* d, const void* s, bool pred) {
    uint32_t da = (uint32_t)__cvta_generic_to_shared(d);
    int sz = pred ? 16 : 0;
    asm volatile("cp.async.cg.shared.global [%0], [%1], 16, %2;" :: "r"(da), "l"(s), "r"(sz) : "memory");
}
#define CP_COMMIT() asm volatile("cp.async.commit_group;" ::: "memory")
#define CP_WAIT1()  asm volatile("cp.async.wait_group 1;" ::: "memory")
#define CP_WAIT0()  asm volatile("cp.async.wait_group 0;" ::: "memory")

// ----- pipelined path (agg2/node1/node2): K=32 chunks, A+B double-buffered -----
__device__ __forceinline__ void warp_gemm32(const char* stg, FragC acc[4][4], int wm, int wn) {
    const __nv_bfloat16* Ah = (const __nv_bfloat16*)stg;
    const __nv_bfloat16* Al = (const __nv_bfloat16*)(stg + OFF_AL);
    const __nv_bfloat16* Bh = (const __nv_bfloat16*)(stg + OFF_BH);
    const __nv_bfloat16* Bl = (const __nv_bfloat16*)(stg + OFF_BL);
#pragma unroll
    for (int kk = 0; kk < 32; kk += 16) {
        wmma::fragment<wmma::matrix_a, 16, 16, 16, __nv_bfloat16, wmma::row_major> ah[4], al[4];
#pragma unroll
        for (int mi = 0; mi < 4; mi++) {
            wmma::load_matrix_sync(ah[mi], Ah + (wm * 64 + mi * 16) * LDA + kk, LDA);
            wmma::load_matrix_sync(al[mi], Al + (wm * 64 + mi * 16) * LDA + kk, LDA);
        }
#pragma unroll
        for (int ni = 0; ni < 4; ni++) {
            wmma::fragment<wmma::matrix_b, 16, 16, 16, __nv_bfloat16, wmma::col_major> bh, bl;
            wmma::load_matrix_sync(bh, Bh + (wn * 64 + ni * 16) * LDB + kk, LDB);
            wmma::load_matrix_sync(bl, Bl + (wn * 64 + ni * 16) * LDB + kk, LDB);
#pragma unroll
            for (int mi = 0; mi < 4; mi++) {
                wmma::mma_sync(acc[mi][ni], ah[mi], bh, acc[mi][ni]);
                wmma::mma_sync(acc[mi][ni], al[mi], bh, acc[mi][ni]);
                wmma::mma_sync(acc[mi][ni], ah[mi], bl, acc[mi][ni]);
            }
        }
    }
}

template<class FA, class FB>
__device__ __forceinline__ void run_pipe(int C, FA&& fA, FB&& fB, char* smem,
                                         FragC acc[4][4], int wm, int wn) {
    fA(0, smem); fB(0, smem); CP_COMMIT();
    if (C > 1) { fA(1, smem + STG); fB(1, smem + STG); CP_COMMIT(); }
    for (int c = 0; c < C; c++) {
        if (c + 2 < C) CP_WAIT1(); else CP_WAIT0();
        __syncthreads();
        warp_gemm32(smem + (c & 1) * STG, acc, wm, wn);
        __syncthreads();
        if (c + 2 < C) {
            char* stg = smem + (c & 1) * STG;
            fA(c + 2, stg); fB(c + 2, stg); CP_COMMIT();
        }
    }
}

// ----- A-resident path (p/edge, K=128): A fully in smem, B 2-stage K=32 -----
__device__ __forceinline__ void warp_gemm32a(const char* smem, int kc, const char* stgB,
                                             FragC acc[4][4], int wm, int wn) {
    const __nv_bfloat16* Ah = (const __nv_bfloat16*)smem;
    const __nv_bfloat16* Al = (const __nv_bfloat16*)(smem + OFF_ALR);
    const __nv_bfloat16* Bh = (const __nv_bfloat16*)stgB;
    const __nv_bfloat16* Bl = (const __nv_bfloat16*)(stgB + 10240);
#pragma unroll
    for (int kk = 0; kk < 32; kk += 16) {
        wmma::fragment<wmma::matrix_a, 16, 16, 16, __nv_bfloat16, wmma::row_major> ah[4], al[4];
#pragma unroll
        for (int mi = 0; mi < 4; mi++) {
            wmma::load_matrix_sync(ah[mi], Ah + (wm * 64 + mi * 16) * LDAF + kc + kk, LDAF);
            wmma::load_matrix_sync(al[mi], Al + (wm * 64 + mi * 16) * LDAF + kc + kk, LDAF);
        }
#pragma unroll
        for (int ni = 0; ni < 4; ni++) {
            wmma::fragment<wmma::matrix_b, 16, 16, 16, __nv_bfloat16, wmma::col_major> bh, bl;
            wmma::load_matrix_sync(bh, Bh + (wn * 64 + ni * 16) * LDB + kk, LDB);
            wmma::load_matrix_sync(bl, Bl + (wn * 64 + ni * 16) * LDB + kk, LDB);
#pragma unroll
            for (int mi = 0; mi < 4; mi++) {
                wmma::mma_sync(acc[mi][ni], ah[mi], bh, acc[mi][ni]);
                wmma::mma_sync(acc[mi][ni], al[mi], bh, acc[mi][ni]);
                wmma::mma_sync(acc[mi][ni], ah[mi], bl, acc[mi][ni]);
            }
        }
    }
}

// B filler for A-resident path: stage s, chunk c (128 N-rows x 32 K hi+lo)
__device__ __forceinline__ void fillB_ares(char* smem, int s, int wof, int K, int n0,
                                           int kc, int tid) {
    char* stg = smem + OFF_B + s * STGB;
    __nv_bfloat16* Bh = (__nv_bfloat16*)stg;
    __nv_bfloat16* Bl = (__nv_bfloat16*)(stg + 10240);
    const __nv_bfloat16* sh = g_wb + wof + (size_t)n0 * K + kc;
    const __nv_bfloat16* sl = sh + WB_HALF;
    for (int i = tid; i < 512; i += 128) {
        int n = i >> 2, kq = (i & 3) * 8;
        cpa16(Bh + n * LDB + kq, sh + (size_t)n * K + kq);
        cpa16(Bl + n * LDB + kq, sl + (size_t)n * K + kq);
    }
}

// run: A already issued as group 0; loop 4 B chunks
__device__ __forceinline__ void run_ares(char* smem, int wof, int n0,
                                         FragC acc[4][4], int tid, int wm, int wn) {
    fillB_ares(smem, 0, wof, 128, n0, 0, tid); CP_COMMIT();
    fillB_ares(smem, 1, wof, 128, n0, 32, tid); CP_COMMIT();
    CP_WAIT1();            // A + B0 landed
    __syncthreads();
    for (int c = 0; c < 4; c++) {
        warp_gemm32a(smem, c * 32, smem + OFF_B + (c & 1) * STGB, acc, wm, wn);
        if (c < 3) {
            __syncthreads();
            if (c + 2 < 4) { fillB_ares(smem, c & 1, wof, 128, n0, (c + 2) * 32, tid); CP_COMMIT(); }
            if (c + 2 < 4) CP_WAIT1(); else CP_WAIT0();
        }
    }
    __syncthreads();       // A/B dead; Cw may overlay
}

__device__ __forceinline__ void store_warpC(float* Cw, FragC acc[4][4]) {
#pragma unroll
    for (int mi = 0; mi < 4; mi++)
#pragma unroll
        for (int ni = 0; ni < 4; ni++)
            wmma::store_matrix_sync(Cw + (mi * 16) * 64 + ni * 16, acc[mi][ni], 64,
                                    wmma::mem_row_major);
}

#define GEMM_VARS() \
    extern __shared__ char smem[]; \
    int tid = threadIdx.x, lane = tid & 31, w = tid >> 5, wm = w & 1, wn = w >> 1; \
    int ny = blockIdx.y; (void)ny; \
    FragC acc[4][4]; \
    _Pragma("unroll") for (int mi = 0; mi < 4; mi++) \
    _Pragma("unroll") for (int ni = 0; ni < 4; ni++) wmma::fill_fragment(acc[mi][ni], 0.f);

#define MAKE_FB(wof, K, n0) \
    auto fB = [&](int c, char* stg) { \
        const __nv_bfloat16* sh = g_wb + (wof) + (size_t)(n0) * (K) + c * 32; \
        const __nv_bfloat16* sl = sh + WB_HALF; \
        __nv_bfloat16* Bh = (__nv_bfloat16*)(stg + OFF_BH); \
        __nv_bfloat16* Bl = (__nv_bfloat16*)(stg + OFF_BL); \
        for (int i = tid; i < 512; i += 128) { \
            int n = i >> 2, kq = (i & 3) * 8; \
            cpa16(Bh + n * LDB + kq, sh + (size_t)n * (K) + kq); \
            cpa16(Bl + n * LDB + kq, sl + (size_t)n * (K) + kq); \
        } \
    };

#define EPILOGUE_SETUP() \
    float* Cw = (float*)smem + w * 4096; \
    store_warpC(Cw, acc); \
    __syncwarp();

// ------------------------- p: P = x @ W1a + b1 (K=128, A-resident) ---------
__global__ __launch_bounds__(128, 2) void p_kernel(const float* __restrict__ b1) {
    GEMM_VARS();
    int m0 = blockIdx.x * 128;
    {   // issue full A (group 0)
        __nv_bfloat16* Ah = (__nv_bfloat16*)smem;
        __nv_bfloat16* Al = (__nv_bfloat16*)(smem + OFF_ALR);
        for (int i = tid; i < 2048; i += 128) {
            int r = i >> 4, q = (i & 15) * 8;
            int n = m0 + r;
            cpa16p(Ah + r * LDAF + q, g_xh + (size_t)n * 128 + q, n < NN);
            cpa16p(Al + r * LDAF + q, g_xl + (size_t)n * 128 + q, n < NN);
        }
        CP_COMMIT();
    }
    run_ares(smem, WOF_W1A, ny * 128, acc, tid, wm, wn);
    EPILOGUE_SETUP();
    for (int i2 = lane; i2 < 1024; i2 += 32) {
        int r = i2 >> 4, c = (i2 & 15) * 4;
        int n = m0 + wm * 64 + r;
        if (n < NN) {
            int col = ny * 128 + wn * 64 + c;
            float4 cv = *(float4*)(Cw + r * 64 + c);
            cv.x += __ldg(&b1[col]);     cv.y += __ldg(&b1[col + 1]);
            cv.z += __ldg(&b1[col + 2]); cv.w += __ldg(&b1[col + 3]);
            *(float4*)(g_P + (size_t)n * HID + col) = cv;
        }
    }
}

// ------------------------- edge: red-scatter relu(ea@W1b + P[row]) ---------
__global__ __launch_bounds__(128, 2) void edge_kernel(const void* __restrict__ ei) {
    GEMM_VARS();
    __shared__ int rs[128], cs[128];
    int e0 = blockIdx.x * 128;
    rs[tid] = load_index(ei, e0 + tid);
    cs[tid] = load_index(ei, (long long)NE + e0 + tid);
    {   // issue full A (group 0)
        __nv_bfloat16* Ah = (__nv_bfloat16*)smem;
        __nv_bfloat16* Al = (__nv_bfloat16*)(smem + OFF_ALR);
        for (int i = tid; i < 2048; i += 128) {
            int r = i >> 4, q = (i & 15) * 8;
            size_t off = (size_t)(e0 + r) * 128 + q;
            cpa16(Ah + r * LDAF + q, g_eah + off);
            cpa16(Al + r * LDAF + q, g_eal + off);
        }
        CP_COMMIT();
    }
    run_ares(smem, WOF_W1B, ny * 128, acc, tid, wm, wn);
    EPILOGUE_SETUP();
    for (int i2 = lane; i2 < 1024; i2 += 32) {
        int r = i2 >> 4, c = (i2 & 15) * 4;
        int lr = wm * 64 + r;
        int col = ny * 128 + wn * 64 + c;
        float4 cv = *(float4*)(Cw + r * 64 + c);
        float4 pv = *(const float4*)(g_P + (size_t)rs[lr] * HID + col);
        float4 v;
        v.x = fmaxf(cv.x + pv.x, 0.f);
        v.y = fmaxf(cv.y + pv.y, 0.f);
        v.z = fmaxf(cv.z + pv.z, 0.f);
        v.w = fmaxf(cv.w + pv.w, 0.f);
        red_add4(g_agg + (size_t)cs[lr] * HID + col, v);
    }
    if (ny == 0) red_add1(&g_cnt[cs[tid]], 1.0f);
}

// ------------------------- agg2: rc*(agg@W2) + b2*ind -> hagg hi/lo --------
__global__ __launch_bounds__(128, 2) void agg2_kernel(const float* __restrict__ b2) {
    GEMM_VARS();
    __shared__ float rcs[128], inds[128];
    int m0 = blockIdx.x * 128;
    {
        int n = m0 + tid;
        float c = (n < NN) ? g_cnt[n] : 0.f;
        rcs[tid] = 1.0f / fmaxf(c, 1.0f);
        inds[tid] = (c > 0.f) ? 1.0f : 0.f;
    }
    auto fA = [&](int c, char* stg) {
        int kc = c * 32;
        __nv_bfloat16* Ah = (__nv_bfloat16*)stg;
        __nv_bfloat16* Al = (__nv_bfloat16*)(stg + OFF_AL);
        for (int i = tid; i < 512; i += 128) {
            int r = i >> 2, q = (i & 3) * 8;
            int n = m0 + r;
            cpa16p(Ah + r * LDA + q, g_ah + (size_t)n * 256 + kc + q, n < NN);
            cpa16p(Al + r * LDA + q, g_al + (size_t)n * 256 + kc + q, n < NN);
        }
    };
    MAKE_FB(WOF_W2, 256, ny * 128);
    run_pipe(8, fA, fB, smem, acc, wm, wn);
    EPILOGUE_SETUP();
    for (int i2 = lane; i2 < 1024; i2 += 32) {
        int r = i2 >> 4, c = (i2 & 15) * 4;
        int n = m0 + wm * 64 + r;
        if (n < NN) {
            int col = ny * 128 + wn * 64 + c;
            float rc = rcs[wm * 64 + r], ind = inds[wm * 64 + r];
            float4 cv = *(float4*)(Cw + r * 64 + c);
            cv.x = cv.x * rc + __ldg(&b2[col]) * ind;
            cv.y = cv.y * rc + __ldg(&b2[col + 1]) * ind;
            cv.z = cv.z * rc + __ldg(&b2[col + 2]) * ind;
            cv.w = cv.w * rc + __ldg(&b2[col + 3]) * ind;
            split_store4(g_hh + (size_t)n * 256 + col, g_hl + (size_t)n * 256 + col, cv);
        }
    }
}

// ------------------------- node1: t = relu([x||hagg||u]@W3+b3) -> t hi/lo --
__global__ __launch_bounds__(128, 2) void node1_kernel(const void* __restrict__ batch,
                                                       const float* __restrict__ b3) {
    GEMM_VARS();
    __shared__ int bts[128];
    int m0 = blockIdx.x * 128;
    {
        int n = m0 + tid;
        int b = (n < NN) ? load_index(batch, n) : 0;
        bts[tid] = (b < 64) ? b : 0;
    }
    __syncthreads();
    auto fA = [&](int c, char* stg) {
        int kc = c * 32;
        __nv_bfloat16* Ah = (__nv_bfloat16*)stg;
        __nv_bfloat16* Al = (__nv_bfloat16*)(stg + OFF_AL);
        for (int i = tid; i < 512; i += 128) {
            int r = i >> 2, q = (i & 3) * 8;
            int n = m0 + r;
            int k = kc + q;
            const __nv_bfloat16 *sh, *sl;
            if (k < 128)      { sh = g_xh + (size_t)n * 128 + k;          sl = g_xl + (size_t)n * 128 + k; }
            else if (k < 384) { sh = g_hh + (size_t)n * 256 + (k - 128);  sl = g_hl + (size_t)n * 256 + (k - 128); }
            else              { sh = g_uh + bts[r] * 64 + (k - 384);      sl = g_ul + bts[r] * 64 + (k - 384); }
            cpa16p(Ah + r * LDA + q, sh, n < NN);
            cpa16p(Al + r * LDA + q, sl, n < NN);
        }
    };
    MAKE_FB(WOF_W3, 448, ny * 128);
    run_pipe(14, fA, fB, smem, acc, wm, wn);
    EPILOGUE_SETUP();
    for (int i2 = lane; i2 < 1024; i2 += 32) {
        int r = i2 >> 4, c = (i2 & 15) * 4;
        int n = m0 + wm * 64 + r;
        if (n < NN) {
            int col = ny * 128 + wn * 64 + c;
            float4 cv = *(float4*)(Cw + r * 64 + c);
            cv.x = fmaxf(cv.x + __ldg(&b3[col]), 0.f);
            cv.y = fmaxf(cv.y + __ldg(&b3[col + 1]), 0.f);
            cv.z = fmaxf(cv.z + __ldg(&b3[col + 2]), 0.f);
            cv.w = fmaxf(cv.w + __ldg(&b3[col + 3]), 0.f);
            split_store4(g_th + (size_t)n * 256 + col, g_tl + (size_t)n * 256 + col, cv);
        }
    }
}

// ------------------------- node2: out = t @ W4 + b4 (K=256, N=128) ---------
__global__ __launch_bounds__(128, 2) void node2_kernel(const float* __restrict__ b4,
                                                       float* __restrict__ out) {
    GEMM_VARS();
    int m0 = blockIdx.x * 128;
    auto fA = [&](int c, char* stg) {
        int kc = c * 32;
        __nv_bfloat16* Ah = (__nv_bfloat16*)stg;
        __nv_bfloat16* Al = (__nv_bfloat16*)(stg + OFF_AL);
        for (int i = tid; i < 512; i += 128) {
            int r = i >> 2, q = (i & 3) * 8;
            int n = m0 + r;
            cpa16p(Ah + r * LDA + q, g_th + (size_t)n * 256 + kc + q, n < NN);
            cpa16p(Al + r * LDA + q, g_tl + (size_t)n * 256 + kc + q, n < NN);
        }
    };
    MAKE_FB(WOF_W4, 256, 0);
    run_pipe(8, fA, fB, smem, acc, wm, wn);
    EPILOGUE_SETUP();
    for (int i2 = lane; i2 < 1024; i2 += 32) {
        int r = i2 >> 4, c = (i2 & 15) * 4;
        int n = m0 + wm * 64 + r;
        if (n < NN) {
            int col = wn * 64 + c;
            float4 cv = *(float4*)(Cw + r * 64 + c);
            cv.x += __ldg(&b4[col]);     cv.y += __ldg(&b4[col + 1]);
            cv.z += __ldg(&b4[col + 2]); cv.w += __ldg(&b4[col + 3]);
            *(float4*)(out + (size_t)n * 128 + col) = cv;
        }
    }
}

// ---------------------------------------------------------------------------
extern "C" void kernel_launch(void* const* d_in, const int* in_sizes, int n_in,
                              void* d_out, int out_size) {
    const float* x     = (const float*)d_in[0];
    const void*  ei    = d_in[1];
    const float* ea    = (const float*)d_in[2];
    const float* u     = (const float*)d_in[3];
    const void*  batch = d_in[4];
    const float* W1    = (const float*)d_in[5];
    const float* b1    = (const float*)d_in[6];
    const float* W2    = (const float*)d_in[7];
    const float* b2    = (const float*)d_in[8];
    const float* W3    = (const float*)d_in[9];
    const float* b3    = (const float*)d_in[10];
    const float* W4    = (const float*)d_in[11];
    const float* b4    = (const float*)d_in[12];
    float* out = (float*)d_out;

    static int attr_done = 0;
    if (!attr_done) {
        cudaFuncSetAttribute(p_kernel,     cudaFuncAttributeMaxDynamicSharedMemorySize, SMEM_ARES);
        cudaFuncSetAttribute(edge_kernel,  cudaFuncAttributeMaxDynamicSharedMemorySize, SMEM_ARES);
        cudaFuncSetAttribute(agg2_kernel,  cudaFuncAttributeMaxDynamicSharedMemorySize, SMEM_PIPE);
        cudaFuncSetAttribute(node1_kernel, cudaFuncAttributeMaxDynamicSharedMemorySize, SMEM_PIPE);
        cudaFuncSetAttribute(node2_kernel, cudaFuncAttributeMaxDynamicSharedMemorySize, SMEM_PIPE);
        attr_done = 1;
    }

    int nblk = (NN + 127) / 128;
    dim3 g2(nblk, 2), ge(NE / 128, 2), g1(nblk, 1);
    zero_kernel<<<2048, 256>>>(ei);
    prep_kernel<<<512, 256>>>(W1, W2, W3, W4);
    split_in<<<2048, 256>>>(ea, x, u);
    p_kernel<<<g2, 128, SMEM_ARES>>>(b1);
    edge_kernel<<<ge, 128, SMEM_ARES>>>(ei);
    split_agg<<<1024, 256>>>();
    agg2_kernel<<<g2, 128, SMEM_PIPE>>>(b2);
    node1_kernel<<<g2, 128, SMEM_PIPE>>>(batch, b3);
    node2_kernel<<<g1, 128, SMEM_PIPE>>>(b4, out);
}